// round 17
// baseline (speedup 1.0000x reference)
#include <cuda_runtime.h>
#include <cuda_fp16.h>
#include <math.h>
#include <stdint.h>

#define T_STEPS 512
#define BATCH   64
#define DIM     1024
#define HID     1024
#define GATES   4096
#define NCTA    128

// Scratch (__device__ globals: allocation-free rule)
__device__ float    g_xg[(size_t)T_STEPS * BATCH * GATES]; // x@Wi + b (fp32)
__device__ __half   g_wrh[(size_t)GATES * DIM];            // Wh reordered [n'][k] (persist B)
__device__ uint32_t g_hf[2][4 * 64 * 32 * 4];              // h in A-frag layout, ping-pong
__device__ uint32_t g_xF[(size_t)T_STEPS * 4 * 64 * 32 * 4]; // x in A-frag layout (64MB)
__device__ uint32_t g_wiF[(size_t)512 * 64 * 32 * 2];      // Wi in B-frag layout (8MB)
__device__ unsigned g_flags[NCTA * 64];                    // per-CTA flag, 256B stride

#define HFBYTES 131072   // one g_hf buffer: 4 m-blocks x 64 q-blocks x 32 lanes x 16B

// ---------------------------------------------------------------------------
// Helpers
// ---------------------------------------------------------------------------
__device__ __forceinline__ void mma_f16(float* c,
                                        uint32_t a0, uint32_t a1, uint32_t a2, uint32_t a3,
                                        uint32_t b0, uint32_t b1) {
    asm volatile(
        "mma.sync.aligned.m16n8k16.row.col.f32.f16.f16.f32 "
        "{%0,%1,%2,%3}, {%4,%5,%6,%7}, {%8,%9}, {%0,%1,%2,%3};"
        : "+f"(c[0]), "+f"(c[1]), "+f"(c[2]), "+f"(c[3])
        : "r"(a0), "r"(a1), "r"(a2), "r"(a3), "r"(b0), "r"(b1));
}

__device__ __forceinline__ unsigned ld_acq(const unsigned* p) {
    unsigned v;
    asm volatile("ld.acquire.gpu.global.u32 %0, [%1];" : "=r"(v) : "l"(p));
    return v;
}
__device__ __forceinline__ void st_rel(unsigned* p, unsigned v) {
    asm volatile("st.release.gpu.global.u32 [%0], %1;" :: "l"(p), "r"(v) : "memory");
}

__device__ __forceinline__ uint4 ldcg128(const void* p) {
    uint4 v;
    asm volatile("ld.global.cg.v4.u32 {%0,%1,%2,%3}, [%4];"
                 : "=r"(v.x), "=r"(v.y), "=r"(v.z), "=r"(v.w) : "l"(p));
    return v;
}

__device__ __forceinline__ uint32_t smem_u32(const void* p) {
    uint32_t a;
    asm("{ .reg .u64 t; cvta.to.shared.u64 t, %1; cvt.u32.u64 %0, t; }" : "=r"(a) : "l"(p));
    return a;
}

__device__ __forceinline__ float fsig(float x) { return 1.f / (1.f + __expf(-x)); }
__device__ __forceinline__ float ftanh(float x) {
    float e = __expf(-2.f * fabsf(x));
    float r = (1.f - e) / (1.f + e);
    return x < 0.f ? -r : r;
}

#define LDSM4(r0, r1, r2, r3, addr) \
    asm volatile("ldmatrix.sync.aligned.m8n8.x4.shared.b16 {%0,%1,%2,%3}, [%4];" \
                 : "=r"(r0), "=r"(r1), "=r"(r2), "=r"(r3) : "r"(addr))

#define CP_ASYNC16(dst, src) \
    asm volatile("cp.async.cg.shared.global [%0], [%1], 16;" :: "r"(dst), "l"(src))
#define CP_ASYNC8(dst, src) \
    asm volatile("cp.async.ca.shared.global [%0], [%1], 8;" :: "r"(dst), "l"(src))
#define CP_COMMIT() asm volatile("cp.async.commit_group;" ::: "memory")
#define CP_WAIT0()  asm volatile("cp.async.wait_group 0;" ::: "memory")
#define CP_WAIT1()  asm volatile("cp.async.wait_group 1;" ::: "memory")

// ---------------------------------------------------------------------------
// Kernel 0: prep (unchanged from R16 winner).
// ---------------------------------------------------------------------------
__global__ __launch_bounds__(256) void prep_all(const float* __restrict__ x,
                                                const float* __restrict__ Wi,
                                                const float* __restrict__ Wh,
                                                const float* __restrict__ h0) {
    int gtid = blockIdx.x * 256 + threadIdx.x;

    {
        int t = gtid >> 15;
        int rem = gtid & 32767;
        int row = rem >> 9;
        int col = (rem & 511) * 2;
        int m = row >> 4, q = col >> 4, kin = col & 15;
        int lane = ((row & 7) << 2) | ((kin & 7) >> 1);
        int reg = ((row & 15) >> 3) | ((kin >> 3) << 1);
        const float* xs = x + (size_t)t * (BATCH * DIM) + row * DIM + col;
        __half2 hh = __floats2half2_rn(xs[0], xs[1]);
        *(uint32_t*)((char*)g_xF +
            ((size_t)(t * 256 + m * 64 + q) * 32 + lane) * 16 + reg * 4) = *(uint32_t*)&hh;
    }

    if (gtid < 2097152) {
        int reg = gtid & 1, lane = (gtid >> 1) & 31, q = (gtid >> 6) & 63, nb = gtid >> 12;
        int n = nb * 8 + (lane >> 2);
        int k = q * 16 + reg * 8 + (lane & 3) * 2;
        __half2 hh = __floats2half2_rn(Wi[(size_t)k * GATES + n],
                                       Wi[(size_t)(k + 1) * GATES + n]);
        *(uint32_t*)((char*)g_wiF +
            ((size_t)(nb * 64 + q) * 32 + lane) * 8 + reg * 4) = *(uint32_t*)&hh;
    }

    if (gtid < 2097152) {
#pragma unroll
        for (int e = 0; e < 2; e++) {
            int idx = e * (DIM * GATES / 2) + gtid;
            int col = idx & 4095, k = idx >> 12;
            int g = col >> 10, rem = col & 1023;
            int c = rem >> 4, r2 = rem & 15, nhp = r2 >> 3, jj = r2 & 7;
            int np = c * 64 + nhp * 32 + g * 8 + jj;
            g_wrh[(size_t)np * DIM + k] = __float2half_rn(Wh[idx]);
        }
    }

    if (gtid < 32768) {
        int row = gtid >> 9;
        int col = (gtid & 511) * 2;
        int m = row >> 4, q = col >> 4, kin = col & 15;
        int lane = ((row & 7) << 2) | ((kin & 7) >> 1);
        int reg = ((row & 15) >> 3) | ((kin >> 3) << 1);
        __half2 hh = __floats2half2_rn(h0[row * HID + col], h0[row * HID + col + 1]);
        *(uint32_t*)((char*)g_hf +
            ((size_t)(m * 64 + q) * 32 + lane) * 16 + reg * 4) = *(uint32_t*)&hh;
    }

    if (gtid < NCTA) g_flags[gtid << 6] = 0;
}

// ---------------------------------------------------------------------------
// Kernel 1: xg = x @ Wi + b. Now 2 CTAs/SM: windows of 4 q-blocks,
// 32KB/buffer x 3 = 96KB smem. 16 windows.
// ---------------------------------------------------------------------------
#define XG_WBYTES 32768                   // one window: A 16KB + B 16KB
#define XG_SMEM   (3 * XG_WBYTES)         // 98304

__device__ __forceinline__ void xg_stage(uint32_t smbase, int buf, int my, int nx,
                                         int w, int tid) {
    uint32_t Ab = smbase + (uint32_t)buf * XG_WBYTES;
    uint32_t Bb = Ab + 16384;
    int q0 = w * 4;
    // A: 1024 slots x 16B  (slot s: mb8 = s>>7, qq = (s>>5)&3, lane = s&31)
#pragma unroll
    for (int u = 0; u < 4; u++) {
        int s = u * 256 + tid;
        int mb8 = s >> 7, qq = (s >> 5) & 3, lane = s & 31;
        const char* src = (const char*)g_xF +
            ((size_t)((my * 2 + (mb8 >> 2)) * 256 + (mb8 & 3) * 64 + q0 + qq) * 32 + lane) * 16;
        CP_ASYNC16(Ab + (uint32_t)s * 16, src);
    }
    // B: 2048 slots x 8B   (slot s: nbq = s>>7, qq = (s>>5)&3, lane = s&31)
#pragma unroll
    for (int u = 0; u < 8; u++) {
        int s = u * 256 + tid;
        int nbq = s >> 7, qq = (s >> 5) & 3, lane = s & 31;
        const char* src = (const char*)g_wiF +
            ((size_t)((nx * 16 + nbq) * 64 + q0 + qq) * 32 + lane) * 8;
        CP_ASYNC8(Bb + (uint32_t)s * 8, src);
    }
    CP_COMMIT();
}

__global__ __launch_bounds__(256, 2) void xg_f16(const float* __restrict__ bias) {
    extern __shared__ char smc[];
    uint32_t smbase = smem_u32(smc);

    int tid = threadIdx.x, wid = tid >> 5, lane = tid & 31;
    int gid = lane >> 2, tig = lane & 3;
    int nx = blockIdx.x, my = blockIdx.y;
    int mh = wid & 1, nq = wid >> 1;

    float acc[4][4][4];
#pragma unroll
    for (int i = 0; i < 4; i++)
#pragma unroll
        for (int j = 0; j < 4; j++)
#pragma unroll
            for (int k = 0; k < 4; k++) acc[i][j][k] = 0.f;

    xg_stage(smbase, 0, my, nx, 0, tid);
    xg_stage(smbase, 1, my, nx, 1, tid);

    for (int w = 0; w < 16; w++) {
        if (w == 15) { CP_WAIT0(); } else { CP_WAIT1(); }
        __syncthreads();
        if (w < 14)
            xg_stage(smbase, (w + 2) % 3, my, nx, w + 2, tid);

        uint32_t Aoff = (uint32_t)((w % 3) * XG_WBYTES);
        uint32_t Boff = Aoff + 16384;
#pragma unroll
        for (int qq = 0; qq < 4; qq++) {
            uint4 av[4];
            uint2 bv[4];
#pragma unroll
            for (int mf = 0; mf < 4; mf++)
                av[mf] = *(const uint4*)(smc + Aoff +
                    (((mh * 4 + mf) * 4 + qq) * 32 + lane) * 16);
#pragma unroll
            for (int nf = 0; nf < 4; nf++)
                bv[nf] = *(const uint2*)(smc + Boff +
                    (((nq * 4 + nf) * 4 + qq) * 32 + lane) * 8);
#pragma unroll
            for (int mf = 0; mf < 4; mf++)
#pragma unroll
                for (int nf = 0; nf < 4; nf++)
                    mma_f16(acc[mf][nf], av[mf].x, av[mf].y, av[mf].z, av[mf].w,
                            bv[nf].x, bv[nf].y);
        }
        __syncthreads();
    }

    int bn = nx * 128;
    float2 bval[4];
#pragma unroll
    for (int nf = 0; nf < 4; nf++)
        bval[nf] = *(const float2*)(bias + bn + nq * 32 + nf * 8 + tig * 2);

#pragma unroll
    for (int mf = 0; mf < 4; mf++) {
        int row = my * 128 + mh * 64 + mf * 16 + gid;
#pragma unroll
        for (int nf = 0; nf < 4; nf++) {
            int col = bn + nq * 32 + nf * 8 + tig * 2;
            *(float2*)(g_xg + (size_t)row * GATES + col) =
                make_float2(acc[mf][nf][0] + bval[nf].x, acc[mf][nf][1] + bval[nf].y);
            *(float2*)(g_xg + (size_t)(row + 8) * GATES + col) =
                make_float2(acc[mf][nf][2] + bval[nf].x, acc[mf][nf][3] + bval[nf].y);
        }
    }
}

// ---------------------------------------------------------------------------
// Kernel 2: persistent recurrence. R16 base + ready-first streaming of q
// blocks: poll all 8 producers in one parallel round (cached ballot mask),
// consume q blocks in readiness order so one slow producer overlaps with
// 7 other blocks' MMAs.
// ---------------------------------------------------------------------------
#define BBYTES 131072
#define CHSZ   544
#define RWSZ   (16 * CHSZ)
#define REDOFF BBYTES
#define PERSIST_SMEM (REDOFF + 8 * RWSZ)   // 200704

__global__ __launch_bounds__(256, 1) void lstm_persist(const float* __restrict__ c0,
                                                       float* __restrict__ out) {
    extern __shared__ uint32_t sm[];
    char* smc = (char*)sm;
    uint32_t sbase = smem_u32(sm);

    int tid = threadIdx.x, wid = tid >> 5, lane = tid & 31;
    int cta = blockIdx.x;
    int c = cta >> 1, mg = cta & 1;
    int ks = wid;
    int n0 = c * 64;

#pragma unroll 4
    for (int u = 0; u < 32; u++) {
        int idx = u * 256 + tid;
        int n = idx >> 7, seg = idx & 127;
        uint4 v = *(const uint4*)((const char*)g_wrh + ((size_t)(n0 + n) * DIM + seg * 8) * 2);
        *(uint4*)(smc + n * 2048 + ((seg * 16) ^ ((n & 7) * 16))) = v;
    }

    int ri = lane & 7;
    uint32_t kbB = (uint32_t)(((lane >> 3) & 1) * 16);
    uint32_t bOff[4], bSw[4];
#pragma unroll
    for (int j = 0; j < 4; j++) {
        int nrow = j * 16 + ((lane >> 4) & 1) * 8 + ri;
        bOff[j] = (uint32_t)(nrow * 2048);
        bSw[j] = (uint32_t)((nrow & 7) * 16);
    }

    int rl = wid * 4 + (lane >> 3);
    int rgl = mg * 32 + rl;
    int nh_t = (lane >> 2) & 1;
    int jj0 = (lane & 3) * 2;
    int hc = c * 16 + nh_t * 8 + jj0;
    int mfE = rl >> 4, rf = rl & 15;
    int dlane = (rf & 7) * 4 + (jj0 >> 1);
    int fb = (rf >> 3) * 2;
    int regE = (rf >> 3) | (nh_t << 1);
    uint32_t hfStoreOff =
        (uint32_t)(((mg * 2 + mfE) * 64 + c) * 32 + dlane) * 16 + regE * 4;

    // flag address polled by this lane (lanes 0-7 only are meaningful)
    const unsigned* pollAddr = &g_flags[(((ks * 8 + (lane & 7)) << 1) | mg) << 6];

    float creg[2];
    creg[0] = c0[(size_t)rgl * HID + hc];
    creg[1] = c0[(size_t)rgl * HID + hc + 1];
    float xv[8];
#pragma unroll
    for (int g = 0; g < 4; g++) {
        xv[g * 2 + 0] = g_xg[(size_t)rgl * GATES + g * 1024 + hc];
        xv[g * 2 + 1] = g_xg[(size_t)rgl * GATES + g * 1024 + hc + 1];
    }
    __syncthreads();

    for (int t = 0; t < T_STEPS; t++) {
        const char* hb = (const char*)g_hf + (size_t)(t & 1) * HFBYTES;

        // ---- ready-first streaming consumption of the 8 q-blocks ----
        unsigned rdy = 0, done = 0;
        int pend[3];
        uint4 pa[3][2];

        auto select_load = [&](int slot) {
            unsigned avail;
            if (t == 0) {
                avail = ~done & 0xffu;
            } else {
                avail = rdy & ~done;
                while (avail == 0) {
                    int f = 1;
                    if (lane < 8)
                        f = (ld_acq(pollAddr) >= (unsigned)t) ? 1 : 0;
                    rdy = __ballot_sync(0xffffffffu, f) & 0xffu;
                    avail = rdy & ~done;
                }
            }
            int qs = __ffs((int)avail) - 1;
            done |= 1u << qs;
            int q = ks * 8 + qs;
#pragma unroll
            for (int mf = 0; mf < 2; mf++)
                pa[slot][mf] = ldcg128(hb +
                    (size_t)(((mg * 2 + mf) * 64 + q) * 32 + lane) * 16);
            pend[slot] = qs;
        };

        select_load(0);
        select_load(1);
        select_load(2);

        float acc[2][8][4];
#pragma unroll
        for (int i = 0; i < 2; i++)
#pragma unroll
            for (int j = 0; j < 8; j++)
#pragma unroll
                for (int k = 0; k < 4; k++) acc[i][j][k] = 0.f;

#pragma unroll
        for (int it = 0; it < 8; it++) {
            int slot = it % 3;
            uint4 A0 = pa[slot][0], A1 = pa[slot][1];
            int qs = pend[slot];
            if (it < 5) select_load(slot);

            int q = ks * 8 + qs;
            uint32_t kB = (uint32_t)(q * 32) + kbB;
            uint32_t bq[16];
#pragma unroll
            for (int j = 0; j < 4; j++)
                LDSM4(bq[j * 4], bq[j * 4 + 1], bq[j * 4 + 2], bq[j * 4 + 3],
                      sbase + bOff[j] + (kB ^ bSw[j]));
#pragma unroll
            for (int nf = 0; nf < 8; nf++) {
                mma_f16(acc[0][nf], A0.x, A0.y, A0.z, A0.w, bq[nf * 2], bq[nf * 2 + 1]);
                mma_f16(acc[1][nf], A1.x, A1.y, A1.z, A1.w, bq[nf * 2], bq[nf * 2 + 1]);
            }
        }

        {
            char* rp = smc + REDOFF + wid * RWSZ + lane * 16;
#pragma unroll
            for (int mf = 0; mf < 2; mf++)
#pragma unroll
                for (int nf = 0; nf < 8; nf++)
                    *(float4*)(rp + (mf * 8 + nf) * CHSZ) = *(const float4*)acc[mf][nf];
        }
        __syncthreads();

        float sg[4][2];
#pragma unroll
        for (int g = 0; g < 4; g++) { sg[g][0] = 0.f; sg[g][1] = 0.f; }
#pragma unroll
        for (int w = 0; w < 8; w++) {
            const char* rp = smc + REDOFF + w * RWSZ +
                             (mfE * 8 + nh_t * 4) * CHSZ + dlane * 16 + fb * 4;
#pragma unroll
            for (int g = 0; g < 4; g++) {
                float2 v = *(const float2*)(rp + g * CHSZ);
                sg[g][0] += v.x; sg[g][1] += v.y;
            }
        }

        float hv[2];
#pragma unroll
        for (int cc = 0; cc < 2; cc++) {
            float iv = fsig(sg[0][cc] + xv[cc]);
            float fv = fsig(sg[1][cc] + xv[2 + cc]);
            float gv = ftanh(sg[2][cc] + xv[4 + cc]);
            float ov = fsig(sg[3][cc] + xv[6 + cc]);
            float cv = fv * creg[cc] + iv * gv;
            creg[cc] = cv;
            hv[cc] = ov * ftanh(cv);
        }

        {
            __half2 hh = __floats2half2_rn(hv[0], hv[1]);
            *(uint32_t*)((char*)g_hf + (size_t)((t + 1) & 1) * HFBYTES + hfStoreOff) =
                *(uint32_t*)&hh;
        }
        __syncthreads();
        if (tid == 0 && t + 1 < T_STEPS)
            st_rel(&g_flags[cta << 6], (unsigned)(t + 1));

        *(float2*)(out + (size_t)t * BATCH * HID + (size_t)rgl * HID + hc) =
            make_float2(hv[0], hv[1]);
        if (t + 1 < T_STEPS) {
            const float* xn = g_xg + (size_t)(t + 1) * BATCH * GATES + (size_t)rgl * GATES;
#pragma unroll
            for (int g = 0; g < 4; g++) {
                xv[g * 2 + 0] = xn[g * 1024 + hc];
                xv[g * 2 + 1] = xn[g * 1024 + hc + 1];
            }
        }
    }
}

// ---------------------------------------------------------------------------
extern "C" void kernel_launch(void* const* d_in, const int* in_sizes, int n_in,
                              void* d_out, int out_size) {
    const float* x  = (const float*)d_in[0];   // [T, B, D]
    const float* c0 = (const float*)d_in[1];   // [B, H]
    const float* h0 = (const float*)d_in[2];   // [B, H]
    const float* Wi = (const float*)d_in[3];   // [D, 4H]
    const float* Wh = (const float*)d_in[4];   // [H, 4H]
    const float* b  = (const float*)d_in[5];   // [4H]
    float* out = (float*)d_out;                // [T, B, H]

    cudaFuncSetAttribute(xg_f16, cudaFuncAttributeMaxDynamicSharedMemorySize, XG_SMEM);
    cudaFuncSetAttribute(lstm_persist, cudaFuncAttributeMaxDynamicSharedMemorySize,
                         PERSIST_SMEM);

    // Prep: all frag-layout conversions + flag reset
    prep_all<<<65536, 256>>>(x, Wi, Wh, h0);

    // Input projection: fp16 m16n8k16, 2 CTAs/SM
    xg_f16<<<dim3(32, 256), 256, XG_SMEM>>>(b);

    // Persistent recurrence: ready-first streaming
    lstm_persist<<<NCTA, 256, PERSIST_SMEM>>>(c0, out);
}